// round 1
// baseline (speedup 1.0000x reference)
#include <cuda_runtime.h>
#include <cuda_bf16.h>

#define N_LAYER  4
#define D_MODEL  1024
#define D_STATE  128
#define D_CONV   4
#define HEADDIM  64
#define NHEADS   32
#define D_INNER  2048
#define CONV_DIM 2304         // D_INNER + 2*D_STATE
#define D_IN_PROJ 4384        // 2*D_INNER + 2*D_STATE + NHEADS
#define LSEQ     1024
#define VOCAB    50288
#define EPS      1e-5f

// ---------------- scratch (static device globals; no allocation) -------------
__device__ float g_x  [LSEQ * D_MODEL];    // residual stream
__device__ float g_u  [LSEQ * D_MODEL];    // normed input / final normed
__device__ float g_zx [LSEQ * D_IN_PROJ];  // in_proj output
__device__ float g_xbc[LSEQ * CONV_DIM];   // conv+silu output
__device__ float g_dt [LSEQ * NHEADS];     // softplus dt
__device__ float g_y  [LSEQ * D_INNER];    // ssd output
__device__ float g_t2 [LSEQ * D_INNER];    // gated-norm output

// ---------------- embedding gather ------------------------------------------
__global__ void embed_kernel(const int* __restrict__ ids,
                             const float* __restrict__ emb,
                             float* __restrict__ x) {
    int idx = blockIdx.x * blockDim.x + threadIdx.x;
    if (idx >= LSEQ * D_MODEL) return;
    int t = idx >> 10;
    int d = idx & 1023;
    x[idx] = emb[(size_t)ids[t] * D_MODEL + d];
}

// ---------------- rmsnorm (optionally gated by z*sigmoid(z)) -----------------
__global__ void rmsnorm_kernel(const float* __restrict__ x, int xs,
                               const float* __restrict__ w,
                               const float* z, int zs,
                               float* __restrict__ out, int D) {
    __shared__ float buf[2048];
    __shared__ float red[8];
    __shared__ float s_scale;
    int t = blockIdx.x;
    int tid = threadIdx.x;

    float ss = 0.f;
    for (int c = tid; c < D; c += blockDim.x) {
        float v = x[(size_t)t * xs + c];
        if (z) {
            float zz = z[(size_t)t * zs + c];
            v *= zz / (1.f + expf(-zz));
        }
        buf[c] = v;
        ss += v * v;
    }
    #pragma unroll
    for (int o = 16; o; o >>= 1) ss += __shfl_xor_sync(0xffffffffu, ss, o);
    if ((tid & 31) == 0) red[tid >> 5] = ss;
    __syncthreads();
    if (tid < 32) {
        float v = (tid < 8) ? red[tid] : 0.f;
        #pragma unroll
        for (int o = 4; o; o >>= 1) v += __shfl_xor_sync(0xffffffffu, v, o);
        if (tid == 0) s_scale = rsqrtf(v / (float)D + EPS);
    }
    __syncthreads();
    float sc = s_scale;
    for (int c = tid; c < D; c += blockDim.x)
        out[(size_t)t * D + c] = buf[c] * sc * w[c];
}

// ---------------- dt = softplus(raw + bias) ----------------------------------
__global__ void dt_kernel(const float* __restrict__ zx,
                          const float* __restrict__ dt_bias,
                          float* __restrict__ dt) {
    int idx = blockIdx.x * blockDim.x + threadIdx.x;
    if (idx >= LSEQ * NHEADS) return;
    int t = idx >> 5;
    int h = idx & 31;
    float v = zx[(size_t)t * D_IN_PROJ + (D_INNER + CONV_DIM) + h] + dt_bias[h];
    dt[idx] = (v > 20.f) ? v : log1pf(expf(v));
}

// ---------------- depthwise causal conv (width 4) + silu ---------------------
__global__ void conv_kernel(const float* __restrict__ zx,
                            const float* __restrict__ w,
                            const float* __restrict__ b,
                            float* __restrict__ out) {
    int idx = blockIdx.x * blockDim.x + threadIdx.x;
    if (idx >= LSEQ * CONV_DIM) return;
    int t = idx / CONV_DIM;
    int c = idx - t * CONV_DIM;
    float acc = b[c];
    const float* wc = w + c * 4;
    #pragma unroll
    for (int j = 0; j < 4; ++j) {
        int tt = t - 3 + j;
        if (tt >= 0) acc += zx[(size_t)tt * D_IN_PROJ + D_INNER + c] * wc[j];
    }
    out[idx] = acc / (1.f + expf(-acc));   // silu
}

// ---------------- SSD sequential recurrence ----------------------------------
// h_t[p,n] = exp(A*dt_t)*h_{t-1}[p,n] + B_t[n]*(x_t[p]*dt_t);  y_t[p] = sum_n C_t[n]*h_t[p,n]
// grid: 32 heads * 8 p-groups = 256 blocks; 256 threads = 8 warps (one p each),
// each lane owns 4 state elems (n = lane, lane+32, lane+64, lane+96).
__global__ void ssd_kernel(const float* __restrict__ xbc,
                           const float* __restrict__ dt,
                           const float* __restrict__ A_log,
                           const float* __restrict__ D_p,
                           float* __restrict__ y) {
    int h  = blockIdx.x >> 3;
    int pg = blockIdx.x & 7;
    int tid = threadIdx.x;
    int w = tid >> 5;           // p within group
    int l = tid & 31;           // lane -> n base
    int p = pg * 8 + w;

    __shared__ float Bs[128], Cs[128];

    float h0 = 0.f, h1 = 0.f, h2 = 0.f, h3 = 0.f;
    float Ah = -expf(A_log[h]);
    float Dh = D_p[h];

    for (int t = 0; t < LSEQ; ++t) {
        const float* row = xbc + (size_t)t * CONV_DIM;
        __syncthreads();
        if (tid < 128) Bs[tid] = row[D_INNER + tid];
        else           Cs[tid - 128] = row[D_INNER + D_STATE + (tid - 128)];
        __syncthreads();

        float dtv  = dt[t * NHEADS + h];
        float e    = expf(Ah * dtv);
        float xraw = row[h * HEADDIM + p];
        float xv   = xraw * dtv;

        float acc;
        h0 = e * h0 + Bs[l      ] * xv;
        h1 = e * h1 + Bs[l + 32 ] * xv;
        h2 = e * h2 + Bs[l + 64 ] * xv;
        h3 = e * h3 + Bs[l + 96 ] * xv;
        acc  = Cs[l      ] * h0;
        acc += Cs[l + 32 ] * h1;
        acc += Cs[l + 64 ] * h2;
        acc += Cs[l + 96 ] * h3;
        #pragma unroll
        for (int o = 16; o; o >>= 1) acc += __shfl_xor_sync(0xffffffffu, acc, o);
        if (l == 0) y[(size_t)t * D_INNER + h * HEADDIM + p] = acc + xraw * Dh;
    }
}

// ---------------- SGEMM (NT): C[m,n] = sum_k A[m,k]*B[n,k] (+ add[m,n]) -------
// 128x128 tile, BK=8, 256 threads, 8x8 per thread. M and K must be /128 and /8.
#define GBM 128
#define GBN 128
#define GBK 8
__global__ __launch_bounds__(256) void sgemm_nt(
    const float* __restrict__ A, const float* __restrict__ B,
    const float* add, float* C, int M, int N, int K) {
    __shared__ float As[GBK][GBM + 4];
    __shared__ float Bs[GBK][GBN + 4];

    int bm = blockIdx.y * GBM;
    int bn = blockIdx.x * GBN;
    int tid = threadIdx.x;
    int tx = tid & 15;         // 16 cols of threads
    int ty = tid >> 4;         // 16 rows of threads

    int lr = tid >> 1;         // 0..127 row within tile
    int lk = (tid & 1) * 4;    // 0 or 4

    float acc[8][8];
    #pragma unroll
    for (int i = 0; i < 8; ++i)
        #pragma unroll
        for (int j = 0; j < 8; ++j) acc[i][j] = 0.f;

    for (int k0 = 0; k0 < K; k0 += GBK) {
        float4 av = *(const float4*)(A + (size_t)(bm + lr) * K + k0 + lk);
        As[lk + 0][lr] = av.x; As[lk + 1][lr] = av.y;
        As[lk + 2][lr] = av.z; As[lk + 3][lr] = av.w;

        int brow = bn + lr;
        float4 bv = make_float4(0.f, 0.f, 0.f, 0.f);
        if (brow < N) bv = *(const float4*)(B + (size_t)brow * K + k0 + lk);
        Bs[lk + 0][lr] = bv.x; Bs[lk + 1][lr] = bv.y;
        Bs[lk + 2][lr] = bv.z; Bs[lk + 3][lr] = bv.w;

        __syncthreads();
        #pragma unroll
        for (int k = 0; k < GBK; ++k) {
            float4 a0 = *(const float4*)&As[k][ty * 8];
            float4 a1 = *(const float4*)&As[k][ty * 8 + 4];
            float4 b0 = *(const float4*)&Bs[k][tx * 8];
            float4 b1 = *(const float4*)&Bs[k][tx * 8 + 4];
            float ar[8] = {a0.x, a0.y, a0.z, a0.w, a1.x, a1.y, a1.z, a1.w};
            float br[8] = {b0.x, b0.y, b0.z, b0.w, b1.x, b1.y, b1.z, b1.w};
            #pragma unroll
            for (int i = 0; i < 8; ++i)
                #pragma unroll
                for (int j = 0; j < 8; ++j)
                    acc[i][j] += ar[i] * br[j];
        }
        __syncthreads();
    }

    #pragma unroll
    for (int i = 0; i < 8; ++i) {
        int row = bm + ty * 8 + i;
        #pragma unroll
        for (int j = 0; j < 8; ++j) {
            int col = bn + tx * 8 + j;
            if (col < N) {
                float v = acc[i][j];
                if (add) v += add[(size_t)row * N + col];
                C[(size_t)row * N + col] = v;
            }
        }
    }
}

// ---------------- orchestration ----------------------------------------------
extern "C" void kernel_launch(void* const* d_in, const int* in_sizes, int n_in,
                              void* d_out, int out_size) {
    const int*   ids       = (const int*)  d_in[0];
    const float* emb       = (const float*)d_in[1];
    const float* norm_ws   = (const float*)d_in[2];
    const float* in_ws     = (const float*)d_in[3];
    const float* conv_ws   = (const float*)d_in[4];
    const float* conv_bs   = (const float*)d_in[5];
    const float* dt_biases = (const float*)d_in[6];
    const float* A_logs    = (const float*)d_in[7];
    const float* Ds        = (const float*)d_in[8];
    const float* gnorm_ws  = (const float*)d_in[9];
    const float* out_ws    = (const float*)d_in[10];
    const float* norm_f_w  = (const float*)d_in[11];
    float* out = (float*)d_out;

    float *x, *u, *zx, *xbc, *dtb, *y, *t2;
    cudaGetSymbolAddress((void**)&x,   g_x);
    cudaGetSymbolAddress((void**)&u,   g_u);
    cudaGetSymbolAddress((void**)&zx,  g_zx);
    cudaGetSymbolAddress((void**)&xbc, g_xbc);
    cudaGetSymbolAddress((void**)&dtb, g_dt);
    cudaGetSymbolAddress((void**)&y,   g_y);
    cudaGetSymbolAddress((void**)&t2,  g_t2);

    embed_kernel<<<(LSEQ * D_MODEL + 255) / 256, 256>>>(ids, emb, x);

    for (int i = 0; i < N_LAYER; ++i) {
        // pre-norm
        rmsnorm_kernel<<<LSEQ, 256>>>(x, D_MODEL, norm_ws + (size_t)i * D_MODEL,
                                      nullptr, 0, u, D_MODEL);
        // in_proj: [1024,1024] x [4384,1024]^T -> [1024,4384]
        sgemm_nt<<<dim3((D_IN_PROJ + GBN - 1) / GBN, LSEQ / GBM), 256>>>(
            u, in_ws + (size_t)i * D_IN_PROJ * D_MODEL, nullptr, zx,
            LSEQ, D_IN_PROJ, D_MODEL);
        // dt
        dt_kernel<<<(LSEQ * NHEADS + 255) / 256, 256>>>(
            zx, dt_biases + (size_t)i * NHEADS, dtb);
        // depthwise conv + silu
        conv_kernel<<<(LSEQ * CONV_DIM + 255) / 256, 256>>>(
            zx, conv_ws + (size_t)i * CONV_DIM * D_CONV,
            conv_bs + (size_t)i * CONV_DIM, xbc);
        // SSD scan
        ssd_kernel<<<NHEADS * 8, 256>>>(
            xbc, dtb, A_logs + (size_t)i * NHEADS, Ds + (size_t)i * NHEADS, y);
        // gated rmsnorm (z from zx cols [0,2048))
        rmsnorm_kernel<<<LSEQ, 256>>>(y, D_INNER, gnorm_ws + (size_t)i * D_INNER,
                                      zx, D_IN_PROJ, t2, D_INNER);
        // out_proj + residual: x = x + t2 @ out_w^T
        sgemm_nt<<<dim3(D_MODEL / GBN, LSEQ / GBM), 256>>>(
            t2, out_ws + (size_t)i * D_MODEL * D_INNER, x, x,
            LSEQ, D_MODEL, D_INNER);
    }

    // final norm + logits
    rmsnorm_kernel<<<LSEQ, 256>>>(x, D_MODEL, norm_f_w, nullptr, 0, u, D_MODEL);
    sgemm_nt<<<dim3((VOCAB + GBN - 1) / GBN, LSEQ / GBM), 256>>>(
        u, emb, nullptr, out, LSEQ, VOCAB, D_MODEL);
}

// round 2
// speedup vs baseline: 1.8647x; 1.8647x over previous
#include <cuda_runtime.h>
#include <cuda_bf16.h>
#include <cstdint>

#define N_LAYER  4
#define D_MODEL  1024
#define D_STATE  128
#define D_CONV   4
#define HEADDIM  64
#define NHEADS   32
#define D_INNER  2048
#define CONV_DIM 2304         // D_INNER + 2*D_STATE
#define D_IN_PROJ 4384        // 2*D_INNER + 2*D_STATE + NHEADS
#define LSEQ     1024
#define VOCAB    50288
#define EPS      1e-5f

// ---------------- scratch (static device globals; no allocation) -------------
__device__ float g_x  [LSEQ * D_MODEL];    // residual stream
__device__ float g_u  [LSEQ * D_MODEL];    // normed input / final normed
__device__ float g_zx [LSEQ * D_IN_PROJ];  // in_proj output
__device__ float g_xbc[LSEQ * CONV_DIM];   // conv+silu output
__device__ float g_dt [LSEQ * NHEADS];     // softplus dt
__device__ float g_y  [LSEQ * D_INNER];    // ssd output
__device__ float g_t2 [LSEQ * D_INNER];    // gated-norm output

// ---------------- embedding gather ------------------------------------------
__global__ void embed_kernel(const int* __restrict__ ids,
                             const float* __restrict__ emb,
                             float* __restrict__ x) {
    int idx = blockIdx.x * blockDim.x + threadIdx.x;
    if (idx >= LSEQ * D_MODEL) return;
    int t = idx >> 10;
    int d = idx & 1023;
    x[idx] = emb[(size_t)ids[t] * D_MODEL + d];
}

// ---------------- rmsnorm (optionally gated by z*sigmoid(z)) -----------------
__global__ void rmsnorm_kernel(const float* __restrict__ x, int xs,
                               const float* __restrict__ w,
                               const float* z, int zs,
                               float* __restrict__ out, int D) {
    __shared__ float buf[2048];
    __shared__ float red[8];
    __shared__ float s_scale;
    int t = blockIdx.x;
    int tid = threadIdx.x;

    float ss = 0.f;
    for (int c = tid; c < D; c += blockDim.x) {
        float v = x[(size_t)t * xs + c];
        if (z) {
            float zz = z[(size_t)t * zs + c];
            v *= zz / (1.f + expf(-zz));
        }
        buf[c] = v;
        ss += v * v;
    }
    #pragma unroll
    for (int o = 16; o; o >>= 1) ss += __shfl_xor_sync(0xffffffffu, ss, o);
    if ((tid & 31) == 0) red[tid >> 5] = ss;
    __syncthreads();
    if (tid < 32) {
        float v = (tid < 8) ? red[tid] : 0.f;
        #pragma unroll
        for (int o = 4; o; o >>= 1) v += __shfl_xor_sync(0xffffffffu, v, o);
        if (tid == 0) s_scale = rsqrtf(v / (float)D + EPS);
    }
    __syncthreads();
    float sc = s_scale;
    for (int c = tid; c < D; c += blockDim.x)
        out[(size_t)t * D + c] = buf[c] * sc * w[c];
}

// ---------------- dt = softplus(raw + bias) ----------------------------------
__global__ void dt_kernel(const float* __restrict__ zx,
                          const float* __restrict__ dt_bias,
                          float* __restrict__ dt) {
    int idx = blockIdx.x * blockDim.x + threadIdx.x;
    if (idx >= LSEQ * NHEADS) return;
    int t = idx >> 5;
    int h = idx & 31;
    float v = zx[(size_t)t * D_IN_PROJ + (D_INNER + CONV_DIM) + h] + dt_bias[h];
    dt[idx] = (v > 20.f) ? v : log1pf(expf(v));
}

// ---------------- depthwise causal conv (width 4) + silu ---------------------
__global__ void conv_kernel(const float* __restrict__ zx,
                            const float* __restrict__ w,
                            const float* __restrict__ b,
                            float* __restrict__ out) {
    int idx = blockIdx.x * blockDim.x + threadIdx.x;
    if (idx >= LSEQ * CONV_DIM) return;
    int t = idx / CONV_DIM;
    int c = idx - t * CONV_DIM;
    float acc = b[c];
    const float* wc = w + c * 4;
    #pragma unroll
    for (int j = 0; j < 4; ++j) {
        int tt = t - 3 + j;
        if (tt >= 0) acc += zx[(size_t)tt * D_IN_PROJ + D_INNER + c] * wc[j];
    }
    out[idx] = acc / (1.f + expf(-acc));   // silu
}

// ---------------- SSD sequential recurrence ----------------------------------
__global__ void ssd_kernel(const float* __restrict__ xbc,
                           const float* __restrict__ dt,
                           const float* __restrict__ A_log,
                           const float* __restrict__ D_p,
                           float* __restrict__ y) {
    int h  = blockIdx.x >> 3;
    int pg = blockIdx.x & 7;
    int tid = threadIdx.x;
    int w = tid >> 5;           // p within group
    int l = tid & 31;           // lane -> n base
    int p = pg * 8 + w;

    __shared__ float Bs[128], Cs[128];

    float h0 = 0.f, h1 = 0.f, h2 = 0.f, h3 = 0.f;
    float Ah = -expf(A_log[h]);
    float Dh = D_p[h];

    for (int t = 0; t < LSEQ; ++t) {
        const float* row = xbc + (size_t)t * CONV_DIM;
        __syncthreads();
        if (tid < 128) Bs[tid] = row[D_INNER + tid];
        else           Cs[tid - 128] = row[D_INNER + D_STATE + (tid - 128)];
        __syncthreads();

        float dtv  = dt[t * NHEADS + h];
        float e    = expf(Ah * dtv);
        float xraw = row[h * HEADDIM + p];
        float xv   = xraw * dtv;

        float acc;
        h0 = e * h0 + Bs[l      ] * xv;
        h1 = e * h1 + Bs[l + 32 ] * xv;
        h2 = e * h2 + Bs[l + 64 ] * xv;
        h3 = e * h3 + Bs[l + 96 ] * xv;
        acc  = Cs[l      ] * h0;
        acc += Cs[l + 32 ] * h1;
        acc += Cs[l + 64 ] * h2;
        acc += Cs[l + 96 ] * h3;
        #pragma unroll
        for (int o = 16; o; o >>= 1) acc += __shfl_xor_sync(0xffffffffu, acc, o);
        if (l == 0) y[(size_t)t * D_INNER + h * HEADDIM + p] = acc + xraw * Dh;
    }
}

// =============================================================================
// bf16x3 split-precision tensor-core GEMM (NT): C[m,n] = sum_k A[m,k]*B[n,k]
// A,B fp32 in gmem; in-kernel split A = hi + lo (bf16 each);
// C ~= Ahi*Bhi + Ahi*Blo + Alo*Bhi with fp32 accumulators (mma.m16n8k16).
// BM=128, BN=128, BK=32, 256 threads (8 warps: 4 in M x 2 in N, 32x64 each).
// =============================================================================
#define BM 128
#define BN 128
#define BKK 32
#define LDSB 40   // padded smem stride in bf16 elems (80 B -> conflict-free ldmatrix)

#define LDSM4(R, addr) asm volatile( \
    "ldmatrix.sync.aligned.m8n8.x4.shared.b16 {%0,%1,%2,%3}, [%4];" \
    : "=r"((R)[0]),"=r"((R)[1]),"=r"((R)[2]),"=r"((R)[3]) : "r"(addr))
#define LDSM2(R, addr) asm volatile( \
    "ldmatrix.sync.aligned.m8n8.x2.shared.b16 {%0,%1}, [%2];" \
    : "=r"((R)[0]),"=r"((R)[1]) : "r"(addr))
#define MMA_BF16(acc, a, b) asm volatile( \
    "mma.sync.aligned.m16n8k16.row.col.f32.bf16.bf16.f32 " \
    "{%0,%1,%2,%3},{%4,%5,%6,%7},{%8,%9},{%0,%1,%2,%3};" \
    : "+f"((acc)[0]),"+f"((acc)[1]),"+f"((acc)[2]),"+f"((acc)[3]) \
    : "r"((a)[0]),"r"((a)[1]),"r"((a)[2]),"r"((a)[3]),"r"((b)[0]),"r"((b)[1]))

__device__ __forceinline__ uint32_t smem_u32(const void* p) {
    return (uint32_t)__cvta_generic_to_shared(p);
}

__device__ __forceinline__ void cvt_store4(__nv_bfloat16* hi, __nv_bfloat16* lo,
                                           float4 v) {
    __nv_bfloat162 h01 = __floats2bfloat162_rn(v.x, v.y);
    __nv_bfloat162 h23 = __floats2bfloat162_rn(v.z, v.w);
    *(__nv_bfloat162*)(hi)     = h01;
    *(__nv_bfloat162*)(hi + 2) = h23;
    float l0 = v.x - __low2float(h01);
    float l1 = v.y - __high2float(h01);
    float l2 = v.z - __low2float(h23);
    float l3 = v.w - __high2float(h23);
    *(__nv_bfloat162*)(lo)     = __floats2bfloat162_rn(l0, l1);
    *(__nv_bfloat162*)(lo + 2) = __floats2bfloat162_rn(l2, l3);
}

__global__ __launch_bounds__(256) void gemm_bf16x3(
    const float* __restrict__ A, const float* __restrict__ B,
    const float* add, float* __restrict__ C, int M, int N, int K) {
    __shared__ __nv_bfloat16 sAhi[BM * LDSB], sAlo[BM * LDSB];
    __shared__ __nv_bfloat16 sBhi[BN * LDSB], sBlo[BN * LDSB];

    int tid  = threadIdx.x;
    int wid  = tid >> 5, lane = tid & 31;
    int wm   = wid & 3;          // M strip (x32)
    int wn   = wid >> 2;         // N strip (x64)
    int bm   = blockIdx.y * BM;
    int bn   = blockIdx.x * BN;

    float acc[2][8][4];
    #pragma unroll
    for (int i = 0; i < 2; ++i)
        #pragma unroll
        for (int j = 0; j < 8; ++j)
            #pragma unroll
            for (int q = 0; q < 4; ++q) acc[i][j][q] = 0.f;

    float4 rA[4], rB[4];

    // --- load tile k0 into registers ---
    #define LOAD_TILE(k0)                                                       \
        _Pragma("unroll")                                                       \
        for (int i = 0; i < 4; ++i) {                                           \
            int f = tid + (i << 8);                                             \
            int row = f >> 3, kk = (f & 7) << 2;                                \
            rA[i] = *(const float4*)(A + (size_t)(bm + row) * K + (k0) + kk);   \
            int brow = bn + row;                                                \
            rB[i] = (brow < N)                                                  \
                ? *(const float4*)(B + (size_t)brow * K + (k0) + kk)            \
                : make_float4(0.f, 0.f, 0.f, 0.f);                              \
        }

    #define STORE_TILE()                                                        \
        _Pragma("unroll")                                                       \
        for (int i = 0; i < 4; ++i) {                                           \
            int f = tid + (i << 8);                                             \
            int row = f >> 3, kk = (f & 7) << 2;                                \
            cvt_store4(&sAhi[row * LDSB + kk], &sAlo[row * LDSB + kk], rA[i]);  \
            cvt_store4(&sBhi[row * LDSB + kk], &sBlo[row * LDSB + kk], rB[i]);  \
        }

    LOAD_TILE(0);
    STORE_TILE();
    __syncthreads();

    int mrow = wm * 32 + (lane & 15);          // A ldmatrix row
    int acol_half = ((lane >> 4) << 3);        // A ldmatrix col offset
    int nrow_base = wn * 64 + (lane & 7);      // B ldmatrix row base
    int bcol_half = ((lane >> 3) & 1) << 3;    // B ldmatrix col offset

    for (int k0 = 0; k0 < K; k0 += BKK) {
        bool more = (k0 + BKK) < K;
        if (more) { LOAD_TILE(k0 + BKK); }

        #pragma unroll
        for (int ks = 0; ks < 2; ++ks) {
            int kb = ks * 16;
            uint32_t ahi[2][4], alo[2][4];
            #pragma unroll
            for (int mi = 0; mi < 2; ++mi) {
                int off = (mrow + mi * 16) * LDSB + kb + acol_half;
                LDSM4(ahi[mi], smem_u32(&sAhi[off]));
                LDSM4(alo[mi], smem_u32(&sAlo[off]));
            }
            uint32_t bhi[8][2], blo[8][2];
            #pragma unroll
            for (int ni = 0; ni < 8; ++ni) {
                int off = (nrow_base + ni * 8) * LDSB + kb + bcol_half;
                LDSM2(bhi[ni], smem_u32(&sBhi[off]));
                LDSM2(blo[ni], smem_u32(&sBlo[off]));
            }
            #pragma unroll
            for (int mi = 0; mi < 2; ++mi)
                #pragma unroll
                for (int ni = 0; ni < 8; ++ni) {
                    MMA_BF16(acc[mi][ni], ahi[mi], bhi[ni]);
                    MMA_BF16(acc[mi][ni], ahi[mi], blo[ni]);
                    MMA_BF16(acc[mi][ni], alo[mi], bhi[ni]);
                }
        }
        __syncthreads();
        if (more) {
            STORE_TILE();
            __syncthreads();
        }
    }

    // --- epilogue ---
    int g = lane >> 2, t4 = lane & 3;
    #pragma unroll
    for (int mi = 0; mi < 2; ++mi) {
        int r0 = bm + wm * 32 + mi * 16 + g;
        #pragma unroll
        for (int ni = 0; ni < 8; ++ni) {
            int col = bn + wn * 64 + ni * 8 + t4 * 2;
            if (col < N) {     // N is even, col even -> covers col+1 too
                float2 v0 = make_float2(acc[mi][ni][0], acc[mi][ni][1]);
                float2 v1 = make_float2(acc[mi][ni][2], acc[mi][ni][3]);
                if (add) {
                    float2 a0 = *(const float2*)(add + (size_t)r0 * N + col);
                    float2 a1 = *(const float2*)(add + (size_t)(r0 + 8) * N + col);
                    v0.x += a0.x; v0.y += a0.y;
                    v1.x += a1.x; v1.y += a1.y;
                }
                *(float2*)(C + (size_t)r0 * N + col)       = v0;
                *(float2*)(C + (size_t)(r0 + 8) * N + col) = v1;
            }
        }
    }
}

// ---------------- orchestration ----------------------------------------------
extern "C" void kernel_launch(void* const* d_in, const int* in_sizes, int n_in,
                              void* d_out, int out_size) {
    const int*   ids       = (const int*)  d_in[0];
    const float* emb       = (const float*)d_in[1];
    const float* norm_ws   = (const float*)d_in[2];
    const float* in_ws     = (const float*)d_in[3];
    const float* conv_ws   = (const float*)d_in[4];
    const float* conv_bs   = (const float*)d_in[5];
    const float* dt_biases = (const float*)d_in[6];
    const float* A_logs    = (const float*)d_in[7];
    const float* Ds        = (const float*)d_in[8];
    const float* gnorm_ws  = (const float*)d_in[9];
    const float* out_ws    = (const float*)d_in[10];
    const float* norm_f_w  = (const float*)d_in[11];
    float* out = (float*)d_out;

    float *x, *u, *zx, *xbc, *dtb, *y, *t2;
    cudaGetSymbolAddress((void**)&x,   g_x);
    cudaGetSymbolAddress((void**)&u,   g_u);
    cudaGetSymbolAddress((void**)&zx,  g_zx);
    cudaGetSymbolAddress((void**)&xbc, g_xbc);
    cudaGetSymbolAddress((void**)&dtb, g_dt);
    cudaGetSymbolAddress((void**)&y,   g_y);
    cudaGetSymbolAddress((void**)&t2,  g_t2);

    embed_kernel<<<(LSEQ * D_MODEL + 255) / 256, 256>>>(ids, emb, x);

    for (int i = 0; i < N_LAYER; ++i) {
        // pre-norm
        rmsnorm_kernel<<<LSEQ, 256>>>(x, D_MODEL, norm_ws + (size_t)i * D_MODEL,
                                      nullptr, 0, u, D_MODEL);
        // in_proj: [1024,1024] x [4384,1024]^T -> [1024,4384]
        gemm_bf16x3<<<dim3((D_IN_PROJ + BN - 1) / BN, LSEQ / BM), 256>>>(
            u, in_ws + (size_t)i * D_IN_PROJ * D_MODEL, nullptr, zx,
            LSEQ, D_IN_PROJ, D_MODEL);
        // dt
        dt_kernel<<<(LSEQ * NHEADS + 255) / 256, 256>>>(
            zx, dt_biases + (size_t)i * NHEADS, dtb);
        // depthwise conv + silu
        conv_kernel<<<(LSEQ * CONV_DIM + 255) / 256, 256>>>(
            zx, conv_ws + (size_t)i * CONV_DIM * D_CONV,
            conv_bs + (size_t)i * CONV_DIM, xbc);
        // SSD scan
        ssd_kernel<<<NHEADS * 8, 256>>>(
            xbc, dtb, A_logs + (size_t)i * NHEADS, Ds + (size_t)i * NHEADS, y);
        // gated rmsnorm (z from zx cols [0,2048))
        rmsnorm_kernel<<<LSEQ, 256>>>(y, D_INNER, gnorm_ws + (size_t)i * D_INNER,
                                      zx, D_IN_PROJ, t2, D_INNER);
        // out_proj + residual: x = x + t2 @ out_w^T
        gemm_bf16x3<<<dim3(D_MODEL / BN, LSEQ / BM), 256>>>(
            t2, out_ws + (size_t)i * D_MODEL * D_INNER, x, x,
            LSEQ, D_MODEL, D_INNER);
    }

    // final norm + logits
    rmsnorm_kernel<<<LSEQ, 256>>>(x, D_MODEL, norm_f_w, nullptr, 0, u, D_MODEL);
    gemm_bf16x3<<<dim3((VOCAB + BN - 1) / BN, LSEQ / BM), 256>>>(
        u, emb, nullptr, out, LSEQ, VOCAB, D_MODEL);
}